// round 3
// baseline (speedup 1.0000x reference)
#include <cuda_runtime.h>
#include <stdint.h>

// Problem constants (validated against in_sizes at launch where possible)
#define T_DIM 20          // timestamp range
#define KEYS  2048        // >= R*T = 2000, padded to pow2
#define EDGE_VEC 4        // int4 vectorization over edges

// key -> bitmask of batches whose (r_index, timestamp) == key
__device__ unsigned int g_mask_table[KEYS];

// ---------------------------------------------------------------------------
// Kernel 1: build the (rel,ts) -> batch bitmask table. One block.
// ---------------------------------------------------------------------------
__global__ void build_table_kernel(const int* __restrict__ r_index,
                                   const int* __restrict__ timestamp,
                                   int B) {
    int i = threadIdx.x;
    for (int k = i; k < KEYS; k += blockDim.x) g_mask_table[k] = 0u;
    __syncthreads();
    if (i < B) {
        int key = r_index[i] * T_DIM + timestamp[i];
        atomicOr(&g_mask_table[key], 1u << i);
    }
}

// ---------------------------------------------------------------------------
// Kernel 2: zero the output [B, N] floats (vectorized).
// ---------------------------------------------------------------------------
__global__ void zero_out_kernel(float4* __restrict__ out4, int n4) {
    int i = blockIdx.x * blockDim.x + threadIdx.x;
    if (i < n4) out4[i] = make_float4(0.f, 0.f, 0.f, 0.f);
}
__global__ void zero_tail_kernel(float* __restrict__ out, int start, int n) {
    int i = start + blockIdx.x * blockDim.x + threadIdx.x;
    if (i < n) out[i] = 0.f;
}

// ---------------------------------------------------------------------------
// Kernel 3: sparse tropical SpMM. Grid-stride over edges, int4 loads of
// rel/ts, shared-memory mask table, predicated gather + atomicMax.
// ---------------------------------------------------------------------------
__global__ void traverse_kernel(const float* __restrict__ h_prob,
                                const float* __restrict__ edge_weight,
                                const int*   __restrict__ edge_head,
                                const int*   __restrict__ edge_tail,
                                const int*   __restrict__ edge_rel,
                                const int*   __restrict__ edge_ts,
                                float* __restrict__ out,
                                int E, int N) {
    __shared__ unsigned int s_table[KEYS];
    for (int k = threadIdx.x; k < KEYS; k += blockDim.x)
        s_table[k] = g_mask_table[k];
    __syncthreads();

    int tid    = blockIdx.x * blockDim.x + threadIdx.x;
    int stride = gridDim.x * blockDim.x * EDGE_VEC;
    int E4     = E & ~(EDGE_VEC - 1);   // vectorizable prefix (E=1e6 -> all of it)

    for (int e = tid * EDGE_VEC; e < E4; e += stride) {
        int4 r4 = *reinterpret_cast<const int4*>(edge_rel + e);
        int4 t4 = *reinterpret_cast<const int4*>(edge_ts  + e);
        int rr[4] = {r4.x, r4.y, r4.z, r4.w};
        int tt[4] = {t4.x, t4.y, t4.z, t4.w};
        #pragma unroll
        for (int j = 0; j < EDGE_VEC; j++) {
            unsigned int m = s_table[rr[j] * T_DIM + tt[j]];
            if (m) {
                int   h  = __ldg(edge_head  + e + j);
                int   t  = __ldg(edge_tail  + e + j);
                float we = __ldg(edge_weight + e + j);
                do {
                    int b = __ffs(m) - 1;
                    m &= m - 1;
                    float v = h_prob[b * N + h] * we;
                    atomicMax(reinterpret_cast<int*>(out + b * N + t),
                              __float_as_int(v));
                } while (m);
            }
        }
    }
    // scalar tail (E not multiple of 4)
    for (int e = E4 + tid; e < E; e += gridDim.x * blockDim.x) {
        unsigned int m = s_table[edge_rel[e] * T_DIM + edge_ts[e]];
        if (m) {
            int   h  = edge_head[e];
            int   t  = edge_tail[e];
            float we = edge_weight[e];
            do {
                int b = __ffs(m) - 1;
                m &= m - 1;
                float v = h_prob[b * N + h] * we;
                atomicMax(reinterpret_cast<int*>(out + b * N + t),
                          __float_as_int(v));
            } while (m);
        }
    }
}

// ---------------------------------------------------------------------------
// Launch
// Inputs (metadata order):
//  0 h_prob      [B*N] f32
//  1 edge_weight [E]   f32
//  2 edge_head   [E]   i32
//  3 edge_tail   [E]   i32
//  4 edge_rel    [E]   i32
//  5 edge_ts     [E]   i32
//  6 r_index     [B]   i32
//  7 timestamp   [B]   i32
//  (possible trailing scalar num_nodes — ignored; N derived from sizes)
// ---------------------------------------------------------------------------
extern "C" void kernel_launch(void* const* d_in, const int* in_sizes, int n_in,
                              void* d_out, int out_size) {
    const float* h_prob      = (const float*)d_in[0];
    const float* edge_weight = (const float*)d_in[1];
    const int*   edge_head   = (const int*)  d_in[2];
    const int*   edge_tail   = (const int*)  d_in[3];
    const int*   edge_rel    = (const int*)  d_in[4];
    const int*   edge_ts     = (const int*)  d_in[5];
    const int*   r_index     = (const int*)  d_in[6];
    const int*   timestamp   = (const int*)  d_in[7];
    float*       out         = (float*)d_out;

    int E = in_sizes[1];
    int B = in_sizes[6];
    int N = out_size / B;

    // 1) pattern table
    build_table_kernel<<<1, 256>>>(r_index, timestamp, B);

    // 2) zero output
    int n4 = out_size / 4;
    if (n4 > 0)
        zero_out_kernel<<<(n4 + 255) / 256, 256>>>((float4*)out, n4);
    int rem = out_size - n4 * 4;
    if (rem > 0)
        zero_tail_kernel<<<1, 256>>>(out, n4 * 4, out_size);

    // 3) traversal: size grid so each thread does ~1 int4 iteration
    int threads = 256;
    int work_items = (E + EDGE_VEC - 1) / EDGE_VEC;
    int blocks = (work_items + threads - 1) / threads;
    if (blocks > 8192) blocks = 8192;
    if (blocks < 1) blocks = 1;
    traverse_kernel<<<blocks, threads>>>(h_prob, edge_weight, edge_head,
                                         edge_tail, edge_rel, edge_ts,
                                         out, E, N);
}